// round 12
// baseline (speedup 1.0000x reference)
#include <cuda_runtime.h>
#include <cuda_fp16.h>
#include <cstdint>

#define B_   8
#define T_   1024
#define D_   1280
#define H_   20
#define MTOT (B_ * T_)   // 8192

// ---------------------------------------------------------------------------
// Scratch (device globals; no allocation allowed)
// ---------------------------------------------------------------------------
__device__ half g_Xf[(size_t)MTOT * D_];      // x as fp16
__device__ half g_Wtf[4 * (size_t)D_ * D_];   // Wq/Wk/Wv/Wo transposed fp16 [N][K]
__device__ half g_Qf[(size_t)MTOT * D_];
__device__ half g_Kf[(size_t)MTOT * D_];
__device__ half g_Vf[(size_t)MTOT * D_];
__device__ half g_Af[(size_t)MTOT * D_];      // attention out fp16

// ---------------------------------------------------------------------------
// PTX helpers (plain sm_103 target — NO tcgen05)
// ---------------------------------------------------------------------------
__device__ __forceinline__ uint32_t smem_u32(const void* p) {
    uint32_t a;
    asm("{ .reg .u64 t; cvta.to.shared.u64 t, %1; cvt.u32.u64 %0, t; }"
        : "=r"(a) : "l"(p));
    return a;
}
__device__ __forceinline__ void cpa16(uint32_t dst, const void* src) {
    asm volatile("cp.async.cg.shared.global [%0], [%1], 16;"
                 :: "r"(dst), "l"(src));
}
__device__ __forceinline__ void cpa_commit() {
    asm volatile("cp.async.commit_group;" ::: "memory");
}
__device__ __forceinline__ void cpa_wait0() { asm volatile("cp.async.wait_group 0;" ::: "memory"); }
__device__ __forceinline__ void cpa_wait1() { asm volatile("cp.async.wait_group 1;" ::: "memory"); }
__device__ __forceinline__ void cpa_wait2() { asm volatile("cp.async.wait_group 2;" ::: "memory"); }
__device__ __forceinline__ void cpa_wait3() { asm volatile("cp.async.wait_group 3;" ::: "memory"); }
__device__ __forceinline__ void ldsm_x4(uint32_t* r, uint32_t addr) {
    asm volatile("ldmatrix.sync.aligned.m8n8.x4.shared.b16 {%0,%1,%2,%3}, [%4];"
                 : "=r"(r[0]), "=r"(r[1]), "=r"(r[2]), "=r"(r[3]) : "r"(addr));
}
__device__ __forceinline__ void ldsm_x4t(uint32_t* r, uint32_t addr) {
    asm volatile("ldmatrix.sync.aligned.m8n8.x4.trans.shared.b16 {%0,%1,%2,%3}, [%4];"
                 : "=r"(r[0]), "=r"(r[1]), "=r"(r[2]), "=r"(r[3]) : "r"(addr));
}
__device__ __forceinline__ void mma_f16(float* c, const uint32_t* a, const uint32_t* b) {
    asm volatile(
        "mma.sync.aligned.m16n8k16.row.col.f32.f16.f16.f32 "
        "{%0,%1,%2,%3}, {%4,%5,%6,%7}, {%8,%9}, {%0,%1,%2,%3};"
        : "+f"(c[0]), "+f"(c[1]), "+f"(c[2]), "+f"(c[3])
        : "r"(a[0]), "r"(a[1]), "r"(a[2]), "r"(a[3]), "r"(b[0]), "r"(b[1]));
}

// ---------------------------------------------------------------------------
// Prepass: fp32 -> fp16 (elementwise)
// ---------------------------------------------------------------------------
__global__ __launch_bounds__(256) void tof16_kernel(
    const float* __restrict__ src, half* __restrict__ dst, int n)
{
    int i = (blockIdx.x * 256 + threadIdx.x) * 4;
    if (i >= n) return;
    float4 v = *(const float4*)(src + i);
    half2* dp = (half2*)(dst + i);
    dp[0] = __floats2half2_rn(v.x, v.y);
    dp[1] = __floats2half2_rn(v.z, v.w);
}

// ---------------------------------------------------------------------------
// Prepass: 4x W[k][n] -> Wt[n][k] fp16 (fused transpose + convert, one launch)
// ---------------------------------------------------------------------------
__global__ __launch_bounds__(256) void transpose4_f16_kernel(
    const float* __restrict__ W0, const float* __restrict__ W1,
    const float* __restrict__ W2, const float* __restrict__ W3,
    half* __restrict__ dstbase)
{
    const int z = blockIdx.z;
    const float* src = (z == 0) ? W0 : (z == 1) ? W1 : (z == 2) ? W2 : W3;
    half* dst = dstbase + (size_t)z * D_ * D_;

    __shared__ float t[32][33];
    int bx = blockIdx.x * 32, by = blockIdx.y * 32;
    int x = bx + threadIdx.x;
    int y = by + threadIdx.y;
#pragma unroll
    for (int i = 0; i < 32; i += 8)
        t[threadIdx.y + i][threadIdx.x] = src[(size_t)(y + i) * D_ + x];
    __syncthreads();
    int x2 = by + threadIdx.x;
    int y2 = bx + threadIdx.y;
#pragma unroll
    for (int i = 0; i < 32; i += 8)
        dst[(size_t)(y2 + i) * D_ + x2] = __float2half_rn(t[threadIdx.x][threadIdx.y + i]);
}

// ---------------------------------------------------------------------------
// fp16 mma.sync GEMM, 256x128 CTA tile, BK=32, 512 threads (16 warps),
// 4-stage cp.async pipeline (R12: depth 2->4 to hide the DRAM latency tail
// exposed in the R11 profile — tensor=26%, issue=10%, DRAM=2.6%).
// C = A[M,K] @ Bt[N,K]^T (+bias). Optional fp32 C, optional fp16 Of.
// ---------------------------------------------------------------------------
#define A_STG 20480                   // 256 rows * 80 B
#define B_STG 10240                   // 128 rows * 80 B
#define STG_BYTES (A_STG + B_STG)     // 30720 per stage
#define NSTG 4
#define F16_SMEM (NSTG * STG_BYTES)   // 122880 B

__global__ __launch_bounds__(512, 1) void gemm_f16_kernel(
    const half* __restrict__ A, const half* __restrict__ Bt,
    const float* __restrict__ bias, float* __restrict__ C,
    half* __restrict__ Of)
{
    extern __shared__ char smem[];
    const uint32_t sb = smem_u32(smem);

    const int tid = threadIdx.x;
    const int wid = tid >> 5, lid = tid & 31;
    const int bm = blockIdx.y * 256;
    const int bn = blockIdx.x * 128;
    const int wm = (wid >> 2) * 64;       // 0..192
    const int wn = (wid & 3) * 32;        // 0..96

    // A loads: 2 threads/row, 2x16B each
    const int larow = tid >> 1;           // 0..255
    const int laseg = (tid & 1) * 16;     // 0 or 16
    // B loads: 4 threads/row, 1x16B each
    const int lbrow = tid >> 2;           // 0..127
    const int lbseg = (tid & 3) * 16;     // 0,16,32,48

    const int arow = lid & 15;
    const int ak   = (lid >> 4) * 16;
    const int bgrp = lid >> 3;
    const int brow = (lid & 7) + ((bgrp >> 1) << 3);
    const int bk   = (bgrp & 1) * 16;

    float acc[4][4][4];
#pragma unroll
    for (int i = 0; i < 4; i++)
#pragma unroll
        for (int j = 0; j < 4; j++)
#pragma unroll
            for (int k = 0; k < 4; k++) acc[i][j][k] = 0.f;

#define STG_A(stage) (sb + (stage) * STG_BYTES)
#define STG_B(stage) (sb + (stage) * STG_BYTES + A_STG)

#define FLOADSTAGE(kb, stage)                                                  \
    {                                                                          \
        size_t ga = (size_t)(bm + larow) * D_ + (kb) * 32 + laseg / 2;         \
        cpa16(STG_A(stage) + (uint32_t)(larow * 80 + laseg),      A + ga);     \
        cpa16(STG_A(stage) + (uint32_t)(larow * 80 + laseg) + 32, A + ga + 16);\
        size_t gb = (size_t)(bn + lbrow) * D_ + (kb) * 32 + lbseg / 2;         \
        cpa16(STG_B(stage) + (uint32_t)(lbrow * 80 + lbseg), Bt + gb);         \
        cpa_commit();                                                          \
    }

    // Prologue: fill stages 0..2 (3 groups in flight)
    FLOADSTAGE(0, 0);
    FLOADSTAGE(1, 1);
    FLOADSTAGE(2, 2);

    for (int kb = 0; kb < 40; kb++) {
        const int st = kb & 3;
        // Issue load for kb+3 into slot (kb+3)&3 — that slot was consumed at
        // iter kb-1, whose trailing __syncthreads guarantees all warps done.
        if (kb + 3 < 40) {
            FLOADSTAGE(kb + 3, (kb + 3) & 3);
            cpa_wait3();          // 4 groups outstanding -> wait for stage kb
        } else {
            const int rem = 39 - kb;        // groups still outstanding beyond kb
            if      (rem >= 3) cpa_wait3();
            else if (rem == 2) cpa_wait2();
            else if (rem == 1) cpa_wait1();
            else               cpa_wait0();
        }
        __syncthreads();

        const uint32_t aB = STG_A(st), bB = STG_B(st);
#pragma unroll
        for (int kk = 0; kk < 2; kk++) {
            const uint32_t ko = kk * 32;
            uint32_t bh[8];
            ldsm_x4(&bh[0], bB + (uint32_t)(wn + brow)      * 80 + bk + ko);
            ldsm_x4(&bh[4], bB + (uint32_t)(wn + 16 + brow) * 80 + bk + ko);
#pragma unroll
            for (int mt = 0; mt < 4; mt++) {
                uint32_t ah[4];
                ldsm_x4(ah, aB + (uint32_t)(wm + mt * 16 + arow) * 80 + ak + ko);
#pragma unroll
                for (int nt = 0; nt < 4; nt++)
                    mma_f16(acc[mt][nt], ah, &bh[nt * 2]);
            }
        }
        __syncthreads();
    }

    // Epilogue
    const int g = lid >> 2, tg = lid & 3;
#pragma unroll
    for (int mt = 0; mt < 4; mt++) {
#pragma unroll
        for (int nt = 0; nt < 4; nt++) {
            int row = bm + wm + mt * 16 + g;
            int col = bn + wn + nt * 8 + tg * 2;
            float b0 = 0.f, b1 = 0.f;
            if (bias) { b0 = bias[col]; b1 = bias[col + 1]; }
            float v00 = acc[mt][nt][0] + b0, v01 = acc[mt][nt][1] + b1;
            float v10 = acc[mt][nt][2] + b0, v11 = acc[mt][nt][3] + b1;
            if (C) {
                *(float2*)(C + (size_t)row * D_ + col)       = make_float2(v00, v01);
                *(float2*)(C + (size_t)(row + 8) * D_ + col) = make_float2(v10, v11);
            }
            if (Of) {
                *(half2*)(Of + (size_t)row * D_ + col)       = __floats2half2_rn(v00, v01);
                *(half2*)(Of + (size_t)(row + 8) * D_ + col) = __floats2half2_rn(v10, v11);
            }
        }
    }
}

// ---------------------------------------------------------------------------
// Causal flash attention (validated at 142us — kept verbatim).
// fp16 operands, fp32 accum, h2exp2 packed softmax, occupancy 2.
// ---------------------------------------------------------------------------
#define AF_Q 0
#define AF_K(st) (18432 + (st) * 9216)
#define AF_V(st) (46080 + (st) * 9216)
#define ATTN_SMEM 73728

__global__ __launch_bounds__(256, 2) void attn_f16_kernel(
    const half* __restrict__ Qf, const half* __restrict__ Kf,
    const half* __restrict__ Vf, half* __restrict__ Af)
{
    extern __shared__ char smem[];
    const uint32_t sb = smem_u32(smem);

    const int tid = threadIdx.x;
    const int wid = tid >> 5, lid = tid & 31;
    const int bh = blockIdx.x;
    const int b  = bh / H_;
    const int h  = bh % H_;
    const int qb = (gridDim.y - 1) - blockIdx.y;   // heavy blocks first
    const int nkt = 2 * qb + 2;

    const int g  = lid >> 2, tg = lid & 3;
    const int wr = wid * 16;
    const int qrow0 = qb * 128 + wr;

    const int arow = lid & 15;
    const int ak   = (lid >> 4) * 16;
    const int bgrp = lid >> 3;
    const int brow = (lid & 7) + ((bgrp >> 1) << 3);
    const int bk   = (bgrp & 1) * 16;
    const int vrow = (lid & 7) + ((bgrp & 1) << 3);
    const int vck  = (lid >> 4) * 16;

    const float SCL = 0.125f * 1.44269504f;   // DH^-0.5 * log2(e)

    {
        const size_t qgbase = (size_t)(b * T_ + qb * 128) * D_ + h * 64;
#pragma unroll
        for (int i = 0; i < 4; i++) {
            int id = tid + i * 256;
            int r = id >> 3, e = (id & 7) * 8;
            cpa16(sb + AF_Q + (uint32_t)(r * 144 + e * 2), Qf + qgbase + (size_t)r * D_ + e);
        }
    }
#define LOADKV(kt, st)                                                         \
    {                                                                          \
        const size_t kvb = (size_t)(b * T_ + (kt) * 64) * D_ + h * 64;         \
        _Pragma("unroll")                                                      \
        for (int i = 0; i < 2; i++) {                                          \
            int id = tid + i * 256;                                            \
            int r = id >> 3, e = (id & 7) * 8;                                 \
            uint32_t so = (uint32_t)(r * 144 + e * 2);                         \
            size_t go = kvb + (size_t)r * D_ + e;                              \
            cpa16(sb + AF_K(st) + so, Kf + go);                                \
            cpa16(sb + AF_V(st) + so, Vf + go);                                \
        }                                                                      \
        cpa_commit();                                                          \
    }
    LOADKV(0, 0);
    if (nkt > 1) LOADKV(1, 1);

    float m0 = -1e30f, m1 = -1e30f, l0 = 0.f, l1 = 0.f;
    float o[8][4];
#pragma unroll
    for (int j = 0; j < 8; j++)
#pragma unroll
        for (int e = 0; e < 4; e++) o[j][e] = 0.f;

    for (int kt = 0; kt < nkt; kt++) {
        const int st = kt % 3;
        if (kt + 2 < nkt) { LOADKV(kt + 2, (kt + 2) % 3); cpa_wait2(); }
        else if (kt + 1 < nkt) cpa_wait1();
        else cpa_wait0();
        __syncthreads();

        if (kt * 64 <= qrow0 + 15) {
            // ---- S = Q K^T ----
            float s[8][4];
#pragma unroll
            for (int j = 0; j < 8; j++)
#pragma unroll
                for (int e = 0; e < 4; e++) s[j][e] = 0.f;

#pragma unroll
            for (int kc = 0; kc < 4; kc++) {
                uint32_t ah[4];
                ldsm_x4(ah, sb + AF_Q + (uint32_t)(wr + arow) * 144 + kc * 32 + ak);
#pragma unroll
                for (int np = 0; np < 4; np++) {
                    uint32_t kb4[4];
                    ldsm_x4(kb4, sb + AF_K(st) + (uint32_t)(np * 16 + brow) * 144 + kc * 32 + bk);
                    mma_f16(s[np * 2],     ah, &kb4[0]);
                    mma_f16(s[np * 2 + 1], ah, &kb4[2]);
                }
            }

            // ---- causal mask on RAW scores (scale folded into exp2) ----
            const int r0 = qrow0 + g, r1 = r0 + 8;
#pragma unroll
            for (int j = 0; j < 8; j++) {
                int c0 = kt * 64 + j * 8 + 2 * tg;
                s[j][0] = (c0     <= r0) ? s[j][0] : -1e30f;
                s[j][1] = (c0 + 1 <= r0) ? s[j][1] : -1e30f;
                s[j][2] = (c0     <= r1) ? s[j][2] : -1e30f;
                s[j][3] = (c0 + 1 <= r1) ? s[j][3] : -1e30f;
            }

            // ---- online softmax ----
            float mx0 = -1e30f, mx1 = -1e30f;
#pragma unroll
            for (int j = 0; j < 8; j++) {
                mx0 = fmaxf(mx0, fmaxf(s[j][0], s[j][1]));
                mx1 = fmaxf(mx1, fmaxf(s[j][2], s[j][3]));
            }
            mx0 = fmaxf(mx0, __shfl_xor_sync(0xffffffffu, mx0, 1));
            mx0 = fmaxf(mx0, __shfl_xor_sync(0xffffffffu, mx0, 2));
            mx1 = fmaxf(mx1, __shfl_xor_sync(0xffffffffu, mx1, 1));
            mx1 = fmaxf(mx1, __shfl_xor_sync(0xffffffffu, mx1, 2));
            float mn0 = fmaxf(m0, mx0), mn1 = fmaxf(m1, mx1);
            float f0 = exp2f((m0 - mn0) * SCL), f1 = exp2f((m1 - mn1) * SCL);
            m0 = mn0; m1 = mn1;
            const float mnl0 = mn0 * SCL, mnl1 = mn1 * SCL;

            uint32_t p[8][2];
            float rs0 = 0.f, rs1 = 0.f;
#pragma unroll
            for (int j = 0; j < 8; j++) {
                half2 e0 = h2exp2(__floats2half2_rn(fmaf(s[j][0], SCL, -mnl0),
                                                    fmaf(s[j][1], SCL, -mnl0)));
                half2 e1 = h2exp2(__floats2half2_rn(fmaf(s[j][2], SCL, -mnl1),
                                                    fmaf(s[j][3], SCL, -mnl1)));
                p[j][0] = *(uint32_t*)&e0;
                p[j][1] = *(uint32_t*)&e1;
                float2 a = __half22float2(e0); rs0 += a.x + a.y;
                float2 c = __half22float2(e1); rs1 += c.x + c.y;
            }
            rs0 += __shfl_xor_sync(0xffffffffu, rs0, 1);
            rs0 += __shfl_xor_sync(0xffffffffu, rs0, 2);
            rs1 += __shfl_xor_sync(0xffffffffu, rs1, 1);
            rs1 += __shfl_xor_sync(0xffffffffu, rs1, 2);
            l0 = l0 * f0 + rs0;
            l1 = l1 * f1 + rs1;
#pragma unroll
            for (int j = 0; j < 8; j++) {
                o[j][0] *= f0; o[j][1] *= f0;
                o[j][2] *= f1; o[j][3] *= f1;
            }

            // ---- O += P V ----
#pragma unroll
            for (int kc = 0; kc < 4; kc++) {
                const int j0 = 2 * kc, j1 = 2 * kc + 1;
                uint32_t pah[4];
                pah[0] = p[j0][0]; pah[1] = p[j0][1];
                pah[2] = p[j1][0]; pah[3] = p[j1][1];
#pragma unroll
                for (int np = 0; np < 4; np++) {
                    uint32_t vb[4];
                    uint32_t vaddr = (uint32_t)(kc * 16 + vrow) * 144 + np * 32 + vck;
                    ldsm_x4t(vb, sb + AF_V(st) + vaddr);
                    mma_f16(o[np * 2],     pah, &vb[0]);
                    mma_f16(o[np * 2 + 1], pah, &vb[2]);
                }
            }
        }
        __syncthreads();
    }

    // ---- epilogue: normalize, store fp16 ----
    const float inv0 = 1.f / l0, inv1 = 1.f / l1;
    const size_t ob = (size_t)(b * T_ + qrow0) * D_ + h * 64;
#pragma unroll
    for (int j = 0; j < 8; j++) {
        int col = j * 8 + 2 * tg;
        *(half2*)(Af + ob + (size_t)g * D_ + col) =
            __floats2half2_rn(o[j][0] * inv0, o[j][1] * inv0);
        *(half2*)(Af + ob + (size_t)(g + 8) * D_ + col) =
            __floats2half2_rn(o[j][2] * inv1, o[j][3] * inv1);
    }
}

// ---------------------------------------------------------------------------
// Launch. Inputs: 0:x 1:k_cache 2:v_cache 3:mask 4:Wq 5:bq 6:Wk 7:Wv 8:bv 9:Wo 10:bo
// Output: [out | k_cache | v_cache]
// ---------------------------------------------------------------------------
extern "C" void kernel_launch(void* const* d_in, const int* in_sizes, int n_in,
                              void* d_out, int out_size)
{
    (void)in_sizes; (void)n_in; (void)out_size;
    const float* x   = (const float*)d_in[0];
    const float* Wq  = (const float*)d_in[4];
    const float* bq  = (const float*)d_in[5];
    const float* Wk  = (const float*)d_in[6];
    const float* Wv  = (const float*)d_in[7];
    const float* bvp = (const float*)d_in[8];
    const float* Wo  = (const float*)d_in[9];
    const float* bo  = (const float*)d_in[10];

    float* out = (float*)d_out;
    float* kc  = out + (size_t)MTOT * D_;
    float* vc  = kc  + (size_t)MTOT * D_;

    half *Xf, *Wtf, *Qf, *Kf, *Vf, *Af;
    cudaGetSymbolAddress((void**)&Xf,  g_Xf);
    cudaGetSymbolAddress((void**)&Wtf, g_Wtf);
    cudaGetSymbolAddress((void**)&Qf,  g_Qf);
    cudaGetSymbolAddress((void**)&Kf,  g_Kf);
    cudaGetSymbolAddress((void**)&Vf,  g_Vf);
    cudaGetSymbolAddress((void**)&Af,  g_Af);

    const size_t WSZ = (size_t)D_ * D_;
    const int NX = MTOT * D_;

    transpose4_f16_kernel<<<dim3(D_ / 32, D_ / 32, 4), dim3(32, 8)>>>(
        Wq, Wk, Wv, Wo, Wtf);
    tof16_kernel<<<NX / (256 * 4), 256>>>(x, Xf, NX);

    cudaFuncSetAttribute(gemm_f16_kernel,
                         cudaFuncAttributeMaxDynamicSharedMemorySize, F16_SMEM);
    dim3 gg(D_ / 128, MTOT / 256);   // (10, 32), 256-row tiles

    gemm_f16_kernel<<<gg, 512, F16_SMEM>>>(Xf, Wtf + 0 * WSZ, bq,      nullptr, Qf);
    gemm_f16_kernel<<<gg, 512, F16_SMEM>>>(Xf, Wtf + 1 * WSZ, nullptr, kc,      Kf);
    gemm_f16_kernel<<<gg, 512, F16_SMEM>>>(Xf, Wtf + 2 * WSZ, bvp,     vc,      Vf);

    cudaFuncSetAttribute(attn_f16_kernel,
                         cudaFuncAttributeMaxDynamicSharedMemorySize, ATTN_SMEM);
    dim3 ga(B_ * H_, T_ / 128);      // (160, 8)
    attn_f16_kernel<<<ga, 256, ATTN_SMEM>>>(Qf, Kf, Vf, Af);

    gemm_f16_kernel<<<gg, 512, F16_SMEM>>>(Af, Wtf + 3 * WSZ, bo, out, nullptr);
}

// round 15
// speedup vs baseline: 1.3840x; 1.3840x over previous
#include <cuda_runtime.h>
#include <cuda_fp16.h>
#include <cstdint>

#define B_   8
#define T_   1024
#define D_   1280
#define H_   20
#define MTOT (B_ * T_)   // 8192

// ---------------------------------------------------------------------------
// Scratch (device globals; no allocation allowed)
// ---------------------------------------------------------------------------
__device__ half g_Xf[(size_t)MTOT * D_];      // x as fp16
__device__ half g_Wtf[4 * (size_t)D_ * D_];   // Wq/Wk/Wv/Wo transposed fp16 [N][K]
__device__ half g_Qf[(size_t)MTOT * D_];
__device__ half g_Kf[(size_t)MTOT * D_];
__device__ half g_Vf[(size_t)MTOT * D_];
__device__ half g_Af[(size_t)MTOT * D_];      // attention out fp16

// ---------------------------------------------------------------------------
// PTX helpers (plain sm_103 target — NO tcgen05)
// ---------------------------------------------------------------------------
__device__ __forceinline__ uint32_t smem_u32(const void* p) {
    uint32_t a;
    asm("{ .reg .u64 t; cvta.to.shared.u64 t, %1; cvt.u32.u64 %0, t; }"
        : "=r"(a) : "l"(p));
    return a;
}
__device__ __forceinline__ void cpa16(uint32_t dst, const void* src) {
    asm volatile("cp.async.cg.shared.global [%0], [%1], 16;"
                 :: "r"(dst), "l"(src));
}
__device__ __forceinline__ void cpa_commit() {
    asm volatile("cp.async.commit_group;" ::: "memory");
}
__device__ __forceinline__ void cpa_wait0() { asm volatile("cp.async.wait_group 0;" ::: "memory"); }
__device__ __forceinline__ void cpa_wait1() { asm volatile("cp.async.wait_group 1;" ::: "memory"); }
__device__ __forceinline__ void cpa_wait2() { asm volatile("cp.async.wait_group 2;" ::: "memory"); }
__device__ __forceinline__ void ldsm_x4(uint32_t* r, uint32_t addr) {
    asm volatile("ldmatrix.sync.aligned.m8n8.x4.shared.b16 {%0,%1,%2,%3}, [%4];"
                 : "=r"(r[0]), "=r"(r[1]), "=r"(r[2]), "=r"(r[3]) : "r"(addr));
}
__device__ __forceinline__ void ldsm_x4t(uint32_t* r, uint32_t addr) {
    asm volatile("ldmatrix.sync.aligned.m8n8.x4.trans.shared.b16 {%0,%1,%2,%3}, [%4];"
                 : "=r"(r[0]), "=r"(r[1]), "=r"(r[2]), "=r"(r[3]) : "r"(addr));
}
__device__ __forceinline__ void mma_f16(float* c, const uint32_t* a, const uint32_t* b) {
    asm volatile(
        "mma.sync.aligned.m16n8k16.row.col.f32.f16.f16.f32 "
        "{%0,%1,%2,%3}, {%4,%5,%6,%7}, {%8,%9}, {%0,%1,%2,%3};"
        : "+f"(c[0]), "+f"(c[1]), "+f"(c[2]), "+f"(c[3])
        : "r"(a[0]), "r"(a[1]), "r"(a[2]), "r"(a[3]), "r"(b[0]), "r"(b[1]));
}

// ---------------------------------------------------------------------------
// Prepass: fp32 -> fp16 (elementwise)
// ---------------------------------------------------------------------------
__global__ __launch_bounds__(256) void tof16_kernel(
    const float* __restrict__ src, half* __restrict__ dst, int n)
{
    int i = (blockIdx.x * 256 + threadIdx.x) * 4;
    if (i >= n) return;
    float4 v = *(const float4*)(src + i);
    half2* dp = (half2*)(dst + i);
    dp[0] = __floats2half2_rn(v.x, v.y);
    dp[1] = __floats2half2_rn(v.z, v.w);
}

// ---------------------------------------------------------------------------
// Prepass: 4x W[k][n] -> Wt[n][k] fp16 (fused transpose + convert, one launch)
// ---------------------------------------------------------------------------
__global__ __launch_bounds__(256) void transpose4_f16_kernel(
    const float* __restrict__ W0, const float* __restrict__ W1,
    const float* __restrict__ W2, const float* __restrict__ W3,
    half* __restrict__ dstbase)
{
    const int z = blockIdx.z;
    const float* src = (z == 0) ? W0 : (z == 1) ? W1 : (z == 2) ? W2 : W3;
    half* dst = dstbase + (size_t)z * D_ * D_;

    __shared__ float t[32][33];
    int bx = blockIdx.x * 32, by = blockIdx.y * 32;
    int x = bx + threadIdx.x;
    int y = by + threadIdx.y;
#pragma unroll
    for (int i = 0; i < 32; i += 8)
        t[threadIdx.y + i][threadIdx.x] = src[(size_t)(y + i) * D_ + x];
    __syncthreads();
    int x2 = by + threadIdx.x;
    int y2 = bx + threadIdx.y;
#pragma unroll
    for (int i = 0; i < 32; i += 8)
        dst[(size_t)(y2 + i) * D_ + x2] = __float2half_rn(t[threadIdx.x][threadIdx.y + i]);
}

// ---------------------------------------------------------------------------
// fp16 GEMM core: 256x128 CTA tile, BK=32, 512 threads (16 warps).
// NSTG=4 ring with lookahead L=2 -> single __syncthreads per iteration:
// the cp.async store target (kb+2)%4 was computed at iter kb-2; iter kb-1's
// barrier orders all its readers before this iteration's stores.
// C = A[M,K] @ Bt[N,K]^T (+bias). Optional fp32 C, optional fp16 Of.
// ---------------------------------------------------------------------------
#define A_STG 20480                   // 256 rows * 80 B
#define B_STG 10240                   // 128 rows * 80 B
#define STG_BYTES (A_STG + B_STG)     // 30720 per stage
#define NSTG 4
#define F16_SMEM (NSTG * STG_BYTES)   // 122880 B

__device__ __forceinline__ void gemm_core(
    const half* __restrict__ A, const half* __restrict__ Bt,
    const float* __restrict__ bias, float* __restrict__ C,
    half* __restrict__ Of, int bm, int bn)
{
    extern __shared__ char smem[];
    const uint32_t sb = smem_u32(smem);

    const int tid = threadIdx.x;
    const int wid = tid >> 5, lid = tid & 31;
    const int wm = (wid >> 2) * 64;       // 0..192
    const int wn = (wid & 3) * 32;        // 0..96

    const int larow = tid >> 1;           // 0..255
    const int laseg = (tid & 1) * 16;     // 0 or 16
    const int lbrow = tid >> 2;           // 0..127
    const int lbseg = (tid & 3) * 16;     // 0,16,32,48

    const int arow = lid & 15;
    const int ak   = (lid >> 4) * 16;
    const int bgrp = lid >> 3;
    const int brow = (lid & 7) + ((bgrp >> 1) << 3);
    const int bk   = (bgrp & 1) * 16;

    float acc[4][4][4];
#pragma unroll
    for (int i = 0; i < 4; i++)
#pragma unroll
        for (int j = 0; j < 4; j++)
#pragma unroll
            for (int k = 0; k < 4; k++) acc[i][j][k] = 0.f;

#define STG_A(stage) (sb + (stage) * STG_BYTES)
#define STG_B(stage) (sb + (stage) * STG_BYTES + A_STG)

#define FLOADSTAGE(kb, stage)                                                  \
    {                                                                          \
        size_t ga = (size_t)(bm + larow) * D_ + (kb) * 32 + laseg / 2;         \
        cpa16(STG_A(stage) + (uint32_t)(larow * 80 + laseg),      A + ga);     \
        cpa16(STG_A(stage) + (uint32_t)(larow * 80 + laseg) + 32, A + ga + 16);\
        size_t gb = (size_t)(bn + lbrow) * D_ + (kb) * 32 + lbseg / 2;         \
        cpa16(STG_B(stage) + (uint32_t)(lbrow * 80 + lbseg), Bt + gb);         \
        cpa_commit();                                                          \
    }

    // Prologue: groups for kb=0,1 in flight
    FLOADSTAGE(0, 0);
    FLOADSTAGE(1, 1);

    for (int kb = 0; kb < 40; kb++) {
        const int st = kb & 3;
        if (kb + 2 < 40) {
            FLOADSTAGE(kb + 2, (kb + 2) & 3);  // slot consumed at iter kb-2
            cpa_wait2();                        // groups kb+1, kb+2 outstanding
        } else {
            const int rem = 39 - kb;            // groups beyond kb still in flight
            if      (rem >= 2) cpa_wait2();
            else if (rem == 1) cpa_wait1();
            else               cpa_wait0();
        }
        __syncthreads();                        // single barrier per iter

        const uint32_t aB = STG_A(st), bB = STG_B(st);
#pragma unroll
        for (int kk = 0; kk < 2; kk++) {
            const uint32_t ko = kk * 32;
            uint32_t bh[8];
            ldsm_x4(&bh[0], bB + (uint32_t)(wn + brow)      * 80 + bk + ko);
            ldsm_x4(&bh[4], bB + (uint32_t)(wn + 16 + brow) * 80 + bk + ko);
#pragma unroll
            for (int mt = 0; mt < 4; mt++) {
                uint32_t ah[4];
                ldsm_x4(ah, aB + (uint32_t)(wm + mt * 16 + arow) * 80 + ak + ko);
#pragma unroll
                for (int nt = 0; nt < 4; nt++)
                    mma_f16(acc[mt][nt], ah, &bh[nt * 2]);
            }
        }
    }

    // Epilogue
    const int g = lid >> 2, tg = lid & 3;
#pragma unroll
    for (int mt = 0; mt < 4; mt++) {
#pragma unroll
        for (int nt = 0; nt < 4; nt++) {
            int row = bm + wm + mt * 16 + g;
            int col = bn + wn + nt * 8 + tg * 2;
            float b0 = 0.f, b1 = 0.f;
            if (bias) { b0 = bias[col]; b1 = bias[col + 1]; }
            float v00 = acc[mt][nt][0] + b0, v01 = acc[mt][nt][1] + b1;
            float v10 = acc[mt][nt][2] + b0, v11 = acc[mt][nt][3] + b1;
            if (C) {
                *(float2*)(C + (size_t)row * D_ + col)       = make_float2(v00, v01);
                *(float2*)(C + (size_t)(row + 8) * D_ + col) = make_float2(v10, v11);
            }
            if (Of) {
                *(half2*)(Of + (size_t)row * D_ + col)       = __floats2half2_rn(v00, v01);
                *(half2*)(Of + (size_t)(row + 8) * D_ + col) = __floats2half2_rn(v10, v11);
            }
        }
    }
}

// Fused Q/K/V projection: grid (30, 32) — x-major keeps the 30 CTAs sharing
// one 256-row A block adjacent in schedule order (L2 reuse); kills 2 of the
// 3 wave-tails the separate launches paid (9 -> 7 wave-units).
__global__ __launch_bounds__(512, 1) void gemm_qkv_kernel(
    const half* __restrict__ Xf, const half* __restrict__ Wtf,
    const float* __restrict__ bq, const float* __restrict__ bvp,
    float* __restrict__ kc, float* __restrict__ vc,
    half* __restrict__ Qf, half* __restrict__ Kf, half* __restrict__ Vf)
{
    const int mat = blockIdx.x / 10;          // 0=Q, 1=K, 2=V
    const int bn  = (blockIdx.x % 10) * 128;
    const half* Bt = Wtf + (size_t)mat * D_ * D_;
    const float* bias = (mat == 0) ? bq : (mat == 2) ? bvp : nullptr;
    float* C  = (mat == 1) ? kc : (mat == 2) ? vc : nullptr;
    half*  Of = (mat == 0) ? Qf : (mat == 1) ? Kf : Vf;
    gemm_core(Xf, Bt, bias, C, Of, blockIdx.y * 256, bn);
}

// Single GEMM (O projection)
__global__ __launch_bounds__(512, 1) void gemm_f16_kernel(
    const half* __restrict__ A, const half* __restrict__ Bt,
    const float* __restrict__ bias, float* __restrict__ C,
    half* __restrict__ Of)
{
    gemm_core(A, Bt, bias, C, Of, blockIdx.y * 256, blockIdx.x * 128);
}

// ---------------------------------------------------------------------------
// Causal flash attention (validated at 142us — kept verbatim).
// fp16 operands, fp32 accum, h2exp2 packed softmax, occupancy 2.
// ---------------------------------------------------------------------------
#define AF_Q 0
#define AF_K(st) (18432 + (st) * 9216)
#define AF_V(st) (46080 + (st) * 9216)
#define ATTN_SMEM 73728

__global__ __launch_bounds__(256, 2) void attn_f16_kernel(
    const half* __restrict__ Qf, const half* __restrict__ Kf,
    const half* __restrict__ Vf, half* __restrict__ Af)
{
    extern __shared__ char smem[];
    const uint32_t sb = smem_u32(smem);

    const int tid = threadIdx.x;
    const int wid = tid >> 5, lid = tid & 31;
    const int bh = blockIdx.x;
    const int b  = bh / H_;
    const int h  = bh % H_;
    const int qb = (gridDim.y - 1) - blockIdx.y;   // heavy blocks first
    const int nkt = 2 * qb + 2;

    const int g  = lid >> 2, tg = lid & 3;
    const int wr = wid * 16;
    const int qrow0 = qb * 128 + wr;

    const int arow = lid & 15;
    const int ak   = (lid >> 4) * 16;
    const int bgrp = lid >> 3;
    const int brow = (lid & 7) + ((bgrp >> 1) << 3);
    const int bk   = (bgrp & 1) * 16;
    const int vrow = (lid & 7) + ((bgrp & 1) << 3);
    const int vck  = (lid >> 4) * 16;

    const float SCL = 0.125f * 1.44269504f;   // DH^-0.5 * log2(e)

    {
        const size_t qgbase = (size_t)(b * T_ + qb * 128) * D_ + h * 64;
#pragma unroll
        for (int i = 0; i < 4; i++) {
            int id = tid + i * 256;
            int r = id >> 3, e = (id & 7) * 8;
            cpa16(sb + AF_Q + (uint32_t)(r * 144 + e * 2), Qf + qgbase + (size_t)r * D_ + e);
        }
    }
#define LOADKV(kt, st)                                                         \
    {                                                                          \
        const size_t kvb = (size_t)(b * T_ + (kt) * 64) * D_ + h * 64;         \
        _Pragma("unroll")                                                      \
        for (int i = 0; i < 2; i++) {                                          \
            int id = tid + i * 256;                                            \
            int r = id >> 3, e = (id & 7) * 8;                                 \
            uint32_t so = (uint32_t)(r * 144 + e * 2);                         \
            size_t go = kvb + (size_t)r * D_ + e;                              \
            cpa16(sb + AF_K(st) + so, Kf + go);                                \
            cpa16(sb + AF_V(st) + so, Vf + go);                                \
        }                                                                      \
        cpa_commit();                                                          \
    }
    LOADKV(0, 0);
    if (nkt > 1) LOADKV(1, 1);

    float m0 = -1e30f, m1 = -1e30f, l0 = 0.f, l1 = 0.f;
    float o[8][4];
#pragma unroll
    for (int j = 0; j < 8; j++)
#pragma unroll
        for (int e = 0; e < 4; e++) o[j][e] = 0.f;

    for (int kt = 0; kt < nkt; kt++) {
        const int st = kt % 3;
        if (kt + 2 < nkt) { LOADKV(kt + 2, (kt + 2) % 3); cpa_wait2(); }
        else if (kt + 1 < nkt) cpa_wait1();
        else cpa_wait0();
        __syncthreads();

        if (kt * 64 <= qrow0 + 15) {
            // ---- S = Q K^T ----
            float s[8][4];
#pragma unroll
            for (int j = 0; j < 8; j++)
#pragma unroll
                for (int e = 0; e < 4; e++) s[j][e] = 0.f;

#pragma unroll
            for (int kc = 0; kc < 4; kc++) {
                uint32_t ah[4];
                ldsm_x4(ah, sb + AF_Q + (uint32_t)(wr + arow) * 144 + kc * 32 + ak);
#pragma unroll
                for (int np = 0; np < 4; np++) {
                    uint32_t kb4[4];
                    ldsm_x4(kb4, sb + AF_K(st) + (uint32_t)(np * 16 + brow) * 144 + kc * 32 + bk);
                    mma_f16(s[np * 2],     ah, &kb4[0]);
                    mma_f16(s[np * 2 + 1], ah, &kb4[2]);
                }
            }

            // ---- causal mask on RAW scores (scale folded into exp2) ----
            const int r0 = qrow0 + g, r1 = r0 + 8;
#pragma unroll
            for (int j = 0; j < 8; j++) {
                int c0 = kt * 64 + j * 8 + 2 * tg;
                s[j][0] = (c0     <= r0) ? s[j][0] : -1e30f;
                s[j][1] = (c0 + 1 <= r0) ? s[j][1] : -1e30f;
                s[j][2] = (c0     <= r1) ? s[j][2] : -1e30f;
                s[j][3] = (c0 + 1 <= r1) ? s[j][3] : -1e30f;
            }

            // ---- online softmax ----
            float mx0 = -1e30f, mx1 = -1e30f;
#pragma unroll
            for (int j = 0; j < 8; j++) {
                mx0 = fmaxf(mx0, fmaxf(s[j][0], s[j][1]));
                mx1 = fmaxf(mx1, fmaxf(s[j][2], s[j][3]));
            }
            mx0 = fmaxf(mx0, __shfl_xor_sync(0xffffffffu, mx0, 1));
            mx0 = fmaxf(mx0, __shfl_xor_sync(0xffffffffu, mx0, 2));
            mx1 = fmaxf(mx1, __shfl_xor_sync(0xffffffffu, mx1, 1));
            mx1 = fmaxf(mx1, __shfl_xor_sync(0xffffffffu, mx1, 2));
            float mn0 = fmaxf(m0, mx0), mn1 = fmaxf(m1, mx1);
            float f0 = exp2f((m0 - mn0) * SCL), f1 = exp2f((m1 - mn1) * SCL);
            m0 = mn0; m1 = mn1;
            const float mnl0 = mn0 * SCL, mnl1 = mn1 * SCL;

            uint32_t p[8][2];
            float rs0 = 0.f, rs1 = 0.f;
#pragma unroll
            for (int j = 0; j < 8; j++) {
                half2 e0 = h2exp2(__floats2half2_rn(fmaf(s[j][0], SCL, -mnl0),
                                                    fmaf(s[j][1], SCL, -mnl0)));
                half2 e1 = h2exp2(__floats2half2_rn(fmaf(s[j][2], SCL, -mnl1),
                                                    fmaf(s[j][3], SCL, -mnl1)));
                p[j][0] = *(uint32_t*)&e0;
                p[j][1] = *(uint32_t*)&e1;
                float2 a = __half22float2(e0); rs0 += a.x + a.y;
                float2 c = __half22float2(e1); rs1 += c.x + c.y;
            }
            rs0 += __shfl_xor_sync(0xffffffffu, rs0, 1);
            rs0 += __shfl_xor_sync(0xffffffffu, rs0, 2);
            rs1 += __shfl_xor_sync(0xffffffffu, rs1, 1);
            rs1 += __shfl_xor_sync(0xffffffffu, rs1, 2);
            l0 = l0 * f0 + rs0;
            l1 = l1 * f1 + rs1;
#pragma unroll
            for (int j = 0; j < 8; j++) {
                o[j][0] *= f0; o[j][1] *= f0;
                o[j][2] *= f1; o[j][3] *= f1;
            }

            // ---- O += P V ----
#pragma unroll
            for (int kc = 0; kc < 4; kc++) {
                const int j0 = 2 * kc, j1 = 2 * kc + 1;
                uint32_t pah[4];
                pah[0] = p[j0][0]; pah[1] = p[j0][1];
                pah[2] = p[j1][0]; pah[3] = p[j1][1];
#pragma unroll
                for (int np = 0; np < 4; np++) {
                    uint32_t vb[4];
                    uint32_t vaddr = (uint32_t)(kc * 16 + vrow) * 144 + np * 32 + vck;
                    ldsm_x4t(vb, sb + AF_V(st) + vaddr);
                    mma_f16(o[np * 2],     pah, &vb[0]);
                    mma_f16(o[np * 2 + 1], pah, &vb[2]);
                }
            }
        }
        __syncthreads();
    }

    // ---- epilogue: normalize, store fp16 ----
    const float inv0 = 1.f / l0, inv1 = 1.f / l1;
    const size_t ob = (size_t)(b * T_ + qrow0) * D_ + h * 64;
#pragma unroll
    for (int j = 0; j < 8; j++) {
        int col = j * 8 + 2 * tg;
        *(half2*)(Af + ob + (size_t)g * D_ + col) =
            __floats2half2_rn(o[j][0] * inv0, o[j][1] * inv0);
        *(half2*)(Af + ob + (size_t)(g + 8) * D_ + col) =
            __floats2half2_rn(o[j][2] * inv1, o[j][3] * inv1);
    }
}

// ---------------------------------------------------------------------------
// Launch. Inputs: 0:x 1:k_cache 2:v_cache 3:mask 4:Wq 5:bq 6:Wk 7:Wv 8:bv 9:Wo 10:bo
// Output: [out | k_cache | v_cache]
// ---------------------------------------------------------------------------
extern "C" void kernel_launch(void* const* d_in, const int* in_sizes, int n_in,
                              void* d_out, int out_size)
{
    (void)in_sizes; (void)n_in; (void)out_size;
    const float* x   = (const float*)d_in[0];
    const float* Wq  = (const float*)d_in[4];
    const float* bq  = (const float*)d_in[5];
    const float* Wk  = (const float*)d_in[6];
    const float* Wv  = (const float*)d_in[7];
    const float* bvp = (const float*)d_in[8];
    const float* Wo  = (const float*)d_in[9];
    const float* bo  = (const float*)d_in[10];

    float* out = (float*)d_out;
    float* kc  = out + (size_t)MTOT * D_;
    float* vc  = kc  + (size_t)MTOT * D_;

    half *Xf, *Wtf, *Qf, *Kf, *Vf, *Af;
    cudaGetSymbolAddress((void**)&Xf,  g_Xf);
    cudaGetSymbolAddress((void**)&Wtf, g_Wtf);
    cudaGetSymbolAddress((void**)&Qf,  g_Qf);
    cudaGetSymbolAddress((void**)&Kf,  g_Kf);
    cudaGetSymbolAddress((void**)&Vf,  g_Vf);
    cudaGetSymbolAddress((void**)&Af,  g_Af);

    const size_t WSZ = (size_t)D_ * D_;
    const int NX = MTOT * D_;

    transpose4_f16_kernel<<<dim3(D_ / 32, D_ / 32, 4), dim3(32, 8)>>>(
        Wq, Wk, Wv, Wo, Wtf);
    tof16_kernel<<<NX / (256 * 4), 256>>>(x, Xf, NX);

    cudaFuncSetAttribute(gemm_qkv_kernel,
                         cudaFuncAttributeMaxDynamicSharedMemorySize, F16_SMEM);
    cudaFuncSetAttribute(gemm_f16_kernel,
                         cudaFuncAttributeMaxDynamicSharedMemorySize, F16_SMEM);

    // Fused Q/K/V: one launch, 30x32 = 960 tiles (7 wave-units vs 3x3=9)
    gemm_qkv_kernel<<<dim3(30, MTOT / 256), 512, F16_SMEM>>>(
        Xf, Wtf, bq, bvp, kc, vc, Qf, Kf, Vf);

    cudaFuncSetAttribute(attn_f16_kernel,
                         cudaFuncAttributeMaxDynamicSharedMemorySize, ATTN_SMEM);
    dim3 ga(B_ * H_, T_ / 128);      // (160, 8)
    attn_f16_kernel<<<ga, 256, ATTN_SMEM>>>(Qf, Kf, Vf, Af);

    // O projection
    gemm_f16_kernel<<<dim3(D_ / 128, MTOT / 256), 512, F16_SMEM>>>(
        Af, Wtf + 3 * WSZ, bo, out, nullptr);
}

// round 16
// speedup vs baseline: 1.6179x; 1.1690x over previous
#include <cuda_runtime.h>
#include <cuda_fp16.h>
#include <cstdint>

#define B_   8
#define T_   1024
#define D_   1280
#define H_   20
#define MTOT (B_ * T_)   // 8192

// ---------------------------------------------------------------------------
// Scratch (device globals; no allocation allowed)
// ---------------------------------------------------------------------------
__device__ half g_Xf[(size_t)MTOT * D_];      // x as fp16
__device__ half g_Wtf[4 * (size_t)D_ * D_];   // Wq/Wk/Wv/Wo transposed fp16 [N][K]
__device__ half g_Qf[(size_t)MTOT * D_];
__device__ half g_Kf[(size_t)MTOT * D_];
__device__ half g_Vf[(size_t)MTOT * D_];
__device__ half g_Af[(size_t)MTOT * D_];      // attention out fp16

// ---------------------------------------------------------------------------
// PTX helpers (plain sm_103 target — NO tcgen05)
// ---------------------------------------------------------------------------
__device__ __forceinline__ uint32_t smem_u32(const void* p) {
    uint32_t a;
    asm("{ .reg .u64 t; cvta.to.shared.u64 t, %1; cvt.u32.u64 %0, t; }"
        : "=r"(a) : "l"(p));
    return a;
}
__device__ __forceinline__ void cpa16(uint32_t dst, const void* src) {
    asm volatile("cp.async.cg.shared.global [%0], [%1], 16;"
                 :: "r"(dst), "l"(src));
}
__device__ __forceinline__ void cpa_commit() {
    asm volatile("cp.async.commit_group;" ::: "memory");
}
__device__ __forceinline__ void cpa_wait0() { asm volatile("cp.async.wait_group 0;" ::: "memory"); }
__device__ __forceinline__ void cpa_wait1() { asm volatile("cp.async.wait_group 1;" ::: "memory"); }
__device__ __forceinline__ void cpa_wait2() { asm volatile("cp.async.wait_group 2;" ::: "memory"); }
__device__ __forceinline__ void ldsm_x4(uint32_t* r, uint32_t addr) {
    asm volatile("ldmatrix.sync.aligned.m8n8.x4.shared.b16 {%0,%1,%2,%3}, [%4];"
                 : "=r"(r[0]), "=r"(r[1]), "=r"(r[2]), "=r"(r[3]) : "r"(addr));
}
__device__ __forceinline__ void ldsm_x4t(uint32_t* r, uint32_t addr) {
    asm volatile("ldmatrix.sync.aligned.m8n8.x4.trans.shared.b16 {%0,%1,%2,%3}, [%4];"
                 : "=r"(r[0]), "=r"(r[1]), "=r"(r[2]), "=r"(r[3]) : "r"(addr));
}
__device__ __forceinline__ void mma_f16(float* c, const uint32_t* a, const uint32_t* b) {
    asm volatile(
        "mma.sync.aligned.m16n8k16.row.col.f32.f16.f16.f32 "
        "{%0,%1,%2,%3}, {%4,%5,%6,%7}, {%8,%9}, {%0,%1,%2,%3};"
        : "+f"(c[0]), "+f"(c[1]), "+f"(c[2]), "+f"(c[3])
        : "r"(a[0]), "r"(a[1]), "r"(a[2]), "r"(a[3]), "r"(b[0]), "r"(b[1]));
}

// ---------------------------------------------------------------------------
// Prepass: fp32 -> fp16 (elementwise)
// ---------------------------------------------------------------------------
__global__ __launch_bounds__(256) void tof16_kernel(
    const float* __restrict__ src, half* __restrict__ dst, int n)
{
    int i = (blockIdx.x * 256 + threadIdx.x) * 4;
    if (i >= n) return;
    float4 v = *(const float4*)(src + i);
    half2* dp = (half2*)(dst + i);
    dp[0] = __floats2half2_rn(v.x, v.y);
    dp[1] = __floats2half2_rn(v.z, v.w);
}

// ---------------------------------------------------------------------------
// Prepass: 4x W[k][n] -> Wt[n][k] fp16 (fused transpose + convert, one launch)
// ---------------------------------------------------------------------------
__global__ __launch_bounds__(256) void transpose4_f16_kernel(
    const float* __restrict__ W0, const float* __restrict__ W1,
    const float* __restrict__ W2, const float* __restrict__ W3,
    half* __restrict__ dstbase)
{
    const int z = blockIdx.z;
    const float* src = (z == 0) ? W0 : (z == 1) ? W1 : (z == 2) ? W2 : W3;
    half* dst = dstbase + (size_t)z * D_ * D_;

    __shared__ float t[32][33];
    int bx = blockIdx.x * 32, by = blockIdx.y * 32;
    int x = bx + threadIdx.x;
    int y = by + threadIdx.y;
#pragma unroll
    for (int i = 0; i < 32; i += 8)
        t[threadIdx.y + i][threadIdx.x] = src[(size_t)(y + i) * D_ + x];
    __syncthreads();
    int x2 = by + threadIdx.x;
    int y2 = bx + threadIdx.y;
#pragma unroll
    for (int i = 0; i < 32; i += 8)
        dst[(size_t)(y2 + i) * D_ + x2] = __float2half_rn(t[threadIdx.x][threadIdx.y + i]);
}

// ---------------------------------------------------------------------------
// fp16 GEMM core: 256x128 CTA tile, BK=64, 512 threads (16 warps).
// R16: BK 32->64 halves barrier/wait events (20 iters, 1 barrier each).
// NSTG=3 ring, lookahead 1; slot kb%3 is rewritten only at iter kb+2's
// load-issue, which is after iter kb+1's barrier -> single barrier is safe.
// Row stride 144 B: bank walk r*36 mod 32 distinct -> conflict-free ldmatrix.
// C = A[M,K] @ Bt[N,K]^T (+bias). Optional fp32 C, optional fp16 Of.
// ---------------------------------------------------------------------------
#define RSTR 144                         // bytes per 64-elem row (padded)
#define A_STG (256 * RSTR)               // 36864
#define B_STG (128 * RSTR)               // 18432
#define STG_BYTES (A_STG + B_STG)        // 55296 per stage
#define NSTG 3
#define F16_SMEM (NSTG * STG_BYTES)      // 165888 B
#define NKB (D_ / 64)                    // 20 iterations

__device__ __forceinline__ void gemm_core(
    const half* __restrict__ A, const half* __restrict__ Bt,
    const float* __restrict__ bias, float* __restrict__ C,
    half* __restrict__ Of, int bm, int bn)
{
    extern __shared__ char smem[];
    const uint32_t sb = smem_u32(smem);

    const int tid = threadIdx.x;
    const int wid = tid >> 5, lid = tid & 31;
    const int wm = (wid >> 2) * 64;       // 0..192
    const int wn = (wid & 3) * 32;        // 0..96

    // Loads: 4 threads per 128B row; A covers rows tid>>2 and tid>>2 + 128.
    const int lrow = tid >> 2;            // 0..127
    const int lseg = (tid & 3) * 32;      // byte offset 0,32,64,96

    const int arow = lid & 15;
    const int ak   = (lid >> 4) * 16;
    const int bgrp = lid >> 3;
    const int brow = (lid & 7) + ((bgrp >> 1) << 3);
    const int bk   = (bgrp & 1) * 16;

    float acc[4][4][4];
#pragma unroll
    for (int i = 0; i < 4; i++)
#pragma unroll
        for (int j = 0; j < 4; j++)
#pragma unroll
            for (int k = 0; k < 4; k++) acc[i][j][k] = 0.f;

#define STG_A(stage) (sb + (stage) * STG_BYTES)
#define STG_B(stage) (sb + (stage) * STG_BYTES + A_STG)

#define FLOADSTAGE(kb, stage)                                                  \
    {                                                                          \
        size_t ga0 = (size_t)(bm + lrow) * D_ + (kb) * 64 + lseg / 2;          \
        size_t ga1 = ga0 + (size_t)128 * D_;                                   \
        uint32_t soA0 = (uint32_t)(lrow * RSTR + lseg);                        \
        uint32_t soA1 = soA0 + 128 * RSTR;                                     \
        cpa16(STG_A(stage) + soA0,      A + ga0);                              \
        cpa16(STG_A(stage) + soA0 + 16, A + ga0 + 8);                          \
        cpa16(STG_A(stage) + soA1,      A + ga1);                              \
        cpa16(STG_A(stage) + soA1 + 16, A + ga1 + 8);                          \
        size_t gb = (size_t)(bn + lrow) * D_ + (kb) * 64 + lseg / 2;           \
        uint32_t soB = (uint32_t)(lrow * RSTR + lseg);                         \
        cpa16(STG_B(stage) + soB,      Bt + gb);                               \
        cpa16(STG_B(stage) + soB + 16, Bt + gb + 8);                           \
        cpa_commit();                                                          \
    }

    FLOADSTAGE(0, 0);

    for (int kb = 0; kb < NKB; kb++) {
        const int st = kb % 3;
        if (kb + 1 < NKB) {
            FLOADSTAGE(kb + 1, (kb + 1) % 3);
            cpa_wait1();                  // wait group kb; kb+1 outstanding
        } else {
            cpa_wait0();
        }
        __syncthreads();                  // single barrier per iteration

        const uint32_t aB = STG_A(st), bB = STG_B(st);
#pragma unroll
        for (int kk = 0; kk < 4; kk++) {
            const uint32_t ko = kk * 32;
            uint32_t bh[8];
            ldsm_x4(&bh[0], bB + (uint32_t)(wn + brow)      * RSTR + bk + ko);
            ldsm_x4(&bh[4], bB + (uint32_t)(wn + 16 + brow) * RSTR + bk + ko);
#pragma unroll
            for (int mt = 0; mt < 4; mt++) {
                uint32_t ah[4];
                ldsm_x4(ah, aB + (uint32_t)(wm + mt * 16 + arow) * RSTR + ak + ko);
#pragma unroll
                for (int nt = 0; nt < 4; nt++)
                    mma_f16(acc[mt][nt], ah, &bh[nt * 2]);
            }
        }
    }

    // Epilogue
    const int g = lid >> 2, tg = lid & 3;
#pragma unroll
    for (int mt = 0; mt < 4; mt++) {
#pragma unroll
        for (int nt = 0; nt < 4; nt++) {
            int row = bm + wm + mt * 16 + g;
            int col = bn + wn + nt * 8 + tg * 2;
            float b0 = 0.f, b1 = 0.f;
            if (bias) { b0 = bias[col]; b1 = bias[col + 1]; }
            float v00 = acc[mt][nt][0] + b0, v01 = acc[mt][nt][1] + b1;
            float v10 = acc[mt][nt][2] + b0, v11 = acc[mt][nt][3] + b1;
            if (C) {
                *(float2*)(C + (size_t)row * D_ + col)       = make_float2(v00, v01);
                *(float2*)(C + (size_t)(row + 8) * D_ + col) = make_float2(v10, v11);
            }
            if (Of) {
                *(half2*)(Of + (size_t)row * D_ + col)       = __floats2half2_rn(v00, v01);
                *(half2*)(Of + (size_t)(row + 8) * D_ + col) = __floats2half2_rn(v10, v11);
            }
        }
    }
}

// Fused Q/K/V projection: grid (30, 32), x-major for A-block L2 reuse.
__global__ __launch_bounds__(512, 1) void gemm_qkv_kernel(
    const half* __restrict__ Xf, const half* __restrict__ Wtf,
    const float* __restrict__ bq, const float* __restrict__ bvp,
    float* __restrict__ kc, float* __restrict__ vc,
    half* __restrict__ Qf, half* __restrict__ Kf, half* __restrict__ Vf)
{
    const int mat = blockIdx.x / 10;          // 0=Q, 1=K, 2=V
    const int bn  = (blockIdx.x % 10) * 128;
    const half* Bt = Wtf + (size_t)mat * D_ * D_;
    const float* bias = (mat == 0) ? bq : (mat == 2) ? bvp : nullptr;
    float* C  = (mat == 1) ? kc : (mat == 2) ? vc : nullptr;
    half*  Of = (mat == 0) ? Qf : (mat == 1) ? Kf : Vf;
    gemm_core(Xf, Bt, bias, C, Of, blockIdx.y * 256, bn);
}

// Single GEMM (O projection)
__global__ __launch_bounds__(512, 1) void gemm_f16_kernel(
    const half* __restrict__ A, const half* __restrict__ Bt,
    const float* __restrict__ bias, float* __restrict__ C,
    half* __restrict__ Of)
{
    gemm_core(A, Bt, bias, C, Of, blockIdx.y * 256, blockIdx.x * 128);
}

// ---------------------------------------------------------------------------
// Causal flash attention (validated — kept verbatim).
// fp16 operands, fp32 accum, h2exp2 packed softmax, occupancy 2.
// ---------------------------------------------------------------------------
#define AF_Q 0
#define AF_K(st) (18432 + (st) * 9216)
#define AF_V(st) (46080 + (st) * 9216)
#define ATTN_SMEM 73728

__global__ __launch_bounds__(256, 2) void attn_f16_kernel(
    const half* __restrict__ Qf, const half* __restrict__ Kf,
    const half* __restrict__ Vf, half* __restrict__ Af)
{
    extern __shared__ char smem[];
    const uint32_t sb = smem_u32(smem);

    const int tid = threadIdx.x;
    const int wid = tid >> 5, lid = tid & 31;
    const int bh = blockIdx.x;
    const int b  = bh / H_;
    const int h  = bh % H_;
    const int qb = (gridDim.y - 1) - blockIdx.y;   // heavy blocks first
    const int nkt = 2 * qb + 2;

    const int g  = lid >> 2, tg = lid & 3;
    const int wr = wid * 16;
    const int qrow0 = qb * 128 + wr;

    const int arow = lid & 15;
    const int ak   = (lid >> 4) * 16;
    const int bgrp = lid >> 3;
    const int brow = (lid & 7) + ((bgrp >> 1) << 3);
    const int bk   = (bgrp & 1) * 16;
    const int vrow = (lid & 7) + ((bgrp & 1) << 3);
    const int vck  = (lid >> 4) * 16;

    const float SCL = 0.125f * 1.44269504f;   // DH^-0.5 * log2(e)

    {
        const size_t qgbase = (size_t)(b * T_ + qb * 128) * D_ + h * 64;
#pragma unroll
        for (int i = 0; i < 4; i++) {
            int id = tid + i * 256;
            int r = id >> 3, e = (id & 7) * 8;
            cpa16(sb + AF_Q + (uint32_t)(r * 144 + e * 2), Qf + qgbase + (size_t)r * D_ + e);
        }
    }
#define LOADKV(kt, st)                                                         \
    {                                                                          \
        const size_t kvb = (size_t)(b * T_ + (kt) * 64) * D_ + h * 64;         \
        _Pragma("unroll")                                                      \
        for (int i = 0; i < 2; i++) {                                          \
            int id = tid + i * 256;                                            \
            int r = id >> 3, e = (id & 7) * 8;                                 \
            uint32_t so = (uint32_t)(r * 144 + e * 2);                         \
            size_t go = kvb + (size_t)r * D_ + e;                              \
            cpa16(sb + AF_K(st) + so, Kf + go);                                \
            cpa16(sb + AF_V(st) + so, Vf + go);                                \
        }                                                                      \
        cpa_commit();                                                          \
    }
    LOADKV(0, 0);
    if (nkt > 1) LOADKV(1, 1);

    float m0 = -1e30f, m1 = -1e30f, l0 = 0.f, l1 = 0.f;
    float o[8][4];
#pragma unroll
    for (int j = 0; j < 8; j++)
#pragma unroll
        for (int e = 0; e < 4; e++) o[j][e] = 0.f;

    for (int kt = 0; kt < nkt; kt++) {
        const int st = kt % 3;
        if (kt + 2 < nkt) { LOADKV(kt + 2, (kt + 2) % 3); cpa_wait2(); }
        else if (kt + 1 < nkt) cpa_wait1();
        else cpa_wait0();
        __syncthreads();

        if (kt * 64 <= qrow0 + 15) {
            // ---- S = Q K^T ----
            float s[8][4];
#pragma unroll
            for (int j = 0; j < 8; j++)
#pragma unroll
                for (int e = 0; e < 4; e++) s[j][e] = 0.f;

#pragma unroll
            for (int kc = 0; kc < 4; kc++) {
                uint32_t ah[4];
                ldsm_x4(ah, sb + AF_Q + (uint32_t)(wr + arow) * 144 + kc * 32 + ak);
#pragma unroll
                for (int np = 0; np < 4; np++) {
                    uint32_t kb4[4];
                    ldsm_x4(kb4, sb + AF_K(st) + (uint32_t)(np * 16 + brow) * 144 + kc * 32 + bk);
                    mma_f16(s[np * 2],     ah, &kb4[0]);
                    mma_f16(s[np * 2 + 1], ah, &kb4[2]);
                }
            }

            // ---- causal mask on RAW scores (scale folded into exp2) ----
            const int r0 = qrow0 + g, r1 = r0 + 8;
#pragma unroll
            for (int j = 0; j < 8; j++) {
                int c0 = kt * 64 + j * 8 + 2 * tg;
                s[j][0] = (c0     <= r0) ? s[j][0] : -1e30f;
                s[j][1] = (c0 + 1 <= r0) ? s[j][1] : -1e30f;
                s[j][2] = (c0     <= r1) ? s[j][2] : -1e30f;
                s[j][3] = (c0 + 1 <= r1) ? s[j][3] : -1e30f;
            }

            // ---- online softmax ----
            float mx0 = -1e30f, mx1 = -1e30f;
#pragma unroll
            for (int j = 0; j < 8; j++) {
                mx0 = fmaxf(mx0, fmaxf(s[j][0], s[j][1]));
                mx1 = fmaxf(mx1, fmaxf(s[j][2], s[j][3]));
            }
            mx0 = fmaxf(mx0, __shfl_xor_sync(0xffffffffu, mx0, 1));
            mx0 = fmaxf(mx0, __shfl_xor_sync(0xffffffffu, mx0, 2));
            mx1 = fmaxf(mx1, __shfl_xor_sync(0xffffffffu, mx1, 1));
            mx1 = fmaxf(mx1, __shfl_xor_sync(0xffffffffu, mx1, 2));
            float mn0 = fmaxf(m0, mx0), mn1 = fmaxf(m1, mx1);
            float f0 = exp2f((m0 - mn0) * SCL), f1 = exp2f((m1 - mn1) * SCL);
            m0 = mn0; m1 = mn1;
            const float mnl0 = mn0 * SCL, mnl1 = mn1 * SCL;

            uint32_t p[8][2];
            float rs0 = 0.f, rs1 = 0.f;
#pragma unroll
            for (int j = 0; j < 8; j++) {
                half2 e0 = h2exp2(__floats2half2_rn(fmaf(s[j][0], SCL, -mnl0),
                                                    fmaf(s[j][1], SCL, -mnl0)));
                half2 e1 = h2exp2(__floats2half2_rn(fmaf(s[j][2], SCL, -mnl1),
                                                    fmaf(s[j][3], SCL, -mnl1)));
                p[j][0] = *(uint32_t*)&e0;
                p[j][1] = *(uint32_t*)&e1;
                float2 a = __half22float2(e0); rs0 += a.x + a.y;
                float2 c = __half22float2(e1); rs1 += c.x + c.y;
            }
            rs0 += __shfl_xor_sync(0xffffffffu, rs0, 1);
            rs0 += __shfl_xor_sync(0xffffffffu, rs0, 2);
            rs1 += __shfl_xor_sync(0xffffffffu, rs1, 1);
            rs1 += __shfl_xor_sync(0xffffffffu, rs1, 2);
            l0 = l0 * f0 + rs0;
            l1 = l1 * f1 + rs1;
#pragma unroll
            for (int j = 0; j < 8; j++) {
                o[j][0] *= f0; o[j][1] *= f0;
                o[j][2] *= f1; o[j][3] *= f1;
            }

            // ---- O += P V ----
#pragma unroll
            for (int kc = 0; kc < 4; kc++) {
                const int j0 = 2 * kc, j1 = 2 * kc + 1;
                uint32_t pah[4];
                pah[0] = p[j0][0]; pah[1] = p[j0][1];
                pah[2] = p[j1][0]; pah[3] = p[j1][1];
#pragma unroll
                for (int np = 0; np < 4; np++) {
                    uint32_t vb[4];
                    uint32_t vaddr = (uint32_t)(kc * 16 + vrow) * 144 + np * 32 + vck;
                    ldsm_x4t(vb, sb + AF_V(st) + vaddr);
                    mma_f16(o[np * 2],     pah, &vb[0]);
                    mma_f16(o[np * 2 + 1], pah, &vb[2]);
                }
            }
        }
        __syncthreads();
    }

    // ---- epilogue: normalize, store fp16 ----
    const float inv0 = 1.f / l0, inv1 = 1.f / l1;
    const size_t ob = (size_t)(b * T_ + qrow0) * D_ + h * 64;
#pragma unroll
    for (int j = 0; j < 8; j++) {
        int col = j * 8 + 2 * tg;
        *(half2*)(Af + ob + (size_t)g * D_ + col) =
            __floats2half2_rn(o[j][0] * inv0, o[j][1] * inv0);
        *(half2*)(Af + ob + (size_t)(g + 8) * D_ + col) =
            __floats2half2_rn(o[j][2] * inv1, o[j][3] * inv1);
    }
}

// ---------------------------------------------------------------------------
// Launch. Inputs: 0:x 1:k_cache 2:v_cache 3:mask 4:Wq 5:bq 6:Wk 7:Wv 8:bv 9:Wo 10:bo
// Output: [out | k_cache | v_cache]
// ---------------------------------------------------------------------------
extern "C" void kernel_launch(void* const* d_in, const int* in_sizes, int n_in,
                              void* d_out, int out_size)
{
    (void)in_sizes; (void)n_in; (void)out_size;
    const float* x   = (const float*)d_in[0];
    const float* Wq  = (const float*)d_in[4];
    const float* bq  = (const float*)d_in[5];
    const float* Wk  = (const float*)d_in[6];
    const float* Wv  = (const float*)d_in[7];
    const float* bvp = (const float*)d_in[8];
    const float* Wo  = (const float*)d_in[9];
    const float* bo  = (const float*)d_in[10];

    float* out = (float*)d_out;
    float* kc  = out + (size_t)MTOT * D_;
    float* vc  = kc  + (size_t)MTOT * D_;

    half *Xf, *Wtf, *Qf, *Kf, *Vf, *Af;
    cudaGetSymbolAddress((void**)&Xf,  g_Xf);
    cudaGetSymbolAddress((void**)&Wtf, g_Wtf);
    cudaGetSymbolAddress((void**)&Qf,  g_Qf);
    cudaGetSymbolAddress((void**)&Kf,  g_Kf);
    cudaGetSymbolAddress((void**)&Vf,  g_Vf);
    cudaGetSymbolAddress((void**)&Af,  g_Af);

    const size_t WSZ = (size_t)D_ * D_;
    const int NX = MTOT * D_;

    transpose4_f16_kernel<<<dim3(D_ / 32, D_ / 32, 4), dim3(32, 8)>>>(
        Wq, Wk, Wv, Wo, Wtf);
    tof16_kernel<<<NX / (256 * 4), 256>>>(x, Xf, NX);

    cudaFuncSetAttribute(gemm_qkv_kernel,
                         cudaFuncAttributeMaxDynamicSharedMemorySize, F16_SMEM);
    cudaFuncSetAttribute(gemm_f16_kernel,
                         cudaFuncAttributeMaxDynamicSharedMemorySize, F16_SMEM);

    // Fused Q/K/V: one launch, 30x32 = 960 tiles
    gemm_qkv_kernel<<<dim3(30, MTOT / 256), 512, F16_SMEM>>>(
        Xf, Wtf, bq, bvp, kc, vc, Qf, Kf, Vf);

    cudaFuncSetAttribute(attn_f16_kernel,
                         cudaFuncAttributeMaxDynamicSharedMemorySize, ATTN_SMEM);
    dim3 ga(B_ * H_, T_ / 128);      // (160, 8)
    attn_f16_kernel<<<ga, 256, ATTN_SMEM>>>(Qf, Kf, Vf, Af);

    // O projection
    gemm_f16_kernel<<<dim3(D_ / 128, MTOT / 256), 512, F16_SMEM>>>(
        Af, Wtf + 3 * WSZ, bo, out, nullptr);
}